// round 4
// baseline (speedup 1.0000x reference)
#include <cuda_runtime.h>
#include <cuda_fp16.h>
#include <math.h>

#define NB   64
#define NT   512
#define NIN  512
#define NH   1024
#define NH3  3072
#define GCTA 128

// ---- static device scratch (allocation-free rule) ----
__device__ __half2  g_x16[NB * NT * NIN / 2];
__device__ __half2  g_w16[NH3 * NIN / 2];
__device__ __half2  g_gi0[(size_t)NB * NT * NH3 / 2];  // [t][b][3072] fp16, bias included
__device__ __half2  g_h0[2][NB * NH / 2];
__device__ __half2  g_h1[2][NB * NH / 2];
__device__ unsigned g_bar;

__device__ __forceinline__ float sigm(float x) { return 1.0f / (1.0f + __expf(-x)); }

__device__ __forceinline__ void mma16816(float* c, unsigned a0, unsigned a1,
                                         unsigned a2, unsigned a3,
                                         unsigned b0, unsigned b1) {
    asm volatile(
        "mma.sync.aligned.m16n8k16.row.col.f32.f16.f16.f32 "
        "{%0,%1,%2,%3},{%4,%5,%6,%7},{%8,%9},{%0,%1,%2,%3};\n"
        : "+f"(c[0]), "+f"(c[1]), "+f"(c[2]), "+f"(c[3])
        : "r"(a0), "r"(a1), "r"(a2), "r"(a3), "r"(b0), "r"(b1));
}

__device__ __forceinline__ void grid_barrier(unsigned& target) {
    __syncthreads();
    if (threadIdx.x == 0) {
        __threadfence();
        atomicAdd(&g_bar, 1u);
        unsigned v;
        do {
            asm volatile("ld.global.acquire.gpu.u32 %0, [%1];"
                         : "=r"(v) : "l"(&g_bar) : "memory");
        } while (v < target);
    }
    __syncthreads();
    target += GCTA;
}

// ---- converters (first kernel also resets the barrier: replay-safe) ----
__global__ void k_cvt_x(const float4* __restrict__ x) {
    int i = blockIdx.x * 256 + threadIdx.x;
    if (i == 0) g_bar = 0;
    float4 v = x[i];
    g_x16[i * 2]     = __floats2half2_rn(v.x, v.y);
    g_x16[i * 2 + 1] = __floats2half2_rn(v.z, v.w);
}
__global__ void k_cvt_w(const float4* __restrict__ w) {
    int i = blockIdx.x * 256 + threadIdx.x;
    float4 v = w[i];
    g_w16[i * 2]     = __floats2half2_rn(v.x, v.y);
    g_w16[i * 2 + 1] = __floats2half2_rn(v.z, v.w);
}

// ---- phase A: gi0 = x @ Wih0^T + bih0 (fp16 mma, fp32 accum) ----
__global__ void __launch_bounds__(256) k_gi0(const float* __restrict__ bih0) {
    __shared__ __half2 sA[64 * 32];
    __shared__ __half2 sB[64 * 32];
    const int tid = threadIdx.x, wid = tid >> 5, lane = tid & 31;
    const int wm = wid & 3, wn = wid >> 2, gID = lane >> 2, tg = lane & 3;
    const int m0 = blockIdx.y * 64, n0 = blockIdx.x * 64;
    const uint4* A4 = (const uint4*)g_x16;
    const uint4* B4 = (const uint4*)g_w16;
    const int swz = gID << 2;
    float c[4][4] = {};

    for (int p = 0; p < 8; p++) {
        __syncthreads();
#pragma unroll
        for (int rep = 0; rep < 2; rep++) {
            int idx = rep * 256 + tid, r = idx >> 3, cu = idx & 7;
            int base = (cu * 4) ^ ((r & 7) << 2);
            *(uint4*)&sA[r * 32 + base] = A4[(m0 + r) * 64 + p * 8 + cu];
            *(uint4*)&sB[r * 32 + base] = B4[(n0 + r) * 64 + p * 8 + cu];
        }
        __syncthreads();
#pragma unroll
        for (int ks = 0; ks < 4; ks++) {
            int col = ks * 8 + tg;
            int ra0 = (wm * 16 + gID) * 32, ra1 = ra0 + 8 * 32;
            unsigned a0 = *(const unsigned*)&sA[ra0 + (col ^ swz)];
            unsigned a1 = *(const unsigned*)&sA[ra1 + (col ^ swz)];
            unsigned a2 = *(const unsigned*)&sA[ra0 + ((col + 4) ^ swz)];
            unsigned a3 = *(const unsigned*)&sA[ra1 + ((col + 4) ^ swz)];
#pragma unroll
            for (int nt = 0; nt < 4; nt++) {
                int rb = (wn * 32 + nt * 8 + gID) * 32;
                unsigned b0 = *(const unsigned*)&sB[rb + (col ^ swz)];
                unsigned b1 = *(const unsigned*)&sB[rb + ((col + 4) ^ swz)];
                mma16816(c[nt], a0, a1, a2, a3, b0, b1);
            }
        }
    }
    int mrow = m0 + wm * 16 + gID;
#pragma unroll
    for (int nt = 0; nt < 4; nt++) {
        int nc = n0 + wn * 32 + nt * 8 + tg * 2;
        float b0 = bih0[nc], b1 = bih0[nc + 1];
        int bA = mrow >> 9, tA = mrow & 511;
        g_gi0[((size_t)tA * NB + bA) * 1536 + (nc >> 1)] =
            __floats2half2_rn(c[nt][0] + b0, c[nt][1] + b1);
        int m2 = mrow + 8, bB = m2 >> 9, tB = m2 & 511;
        g_gi0[((size_t)tB * NB + bB) * 1536 + (nc >> 1)] =
            __floats2half2_rn(c[nt][2] + b0, c[nt][3] + b1);
    }
}

// ---- persistent recurrence ----
#define SMEM_BYTES ((36864 + 8192) * 4 + (4608 + 1536 + 512 + 512 + 72) * 4)

__global__ void __launch_bounds__(256, 1) k_gru(
    float* __restrict__ out,
    const float* __restrict__ Whh0, const float* __restrict__ Wih1,
    const float* __restrict__ Whh1,
    const float* __restrict__ bhh0, const float* __restrict__ bih1,
    const float* __restrict__ bhh1,
    const float* __restrict__ encH, int hasFinal) {
    extern __shared__ __align__(16) __half2 smem[];
    __half2* sW   = smem;                 // 3*24*512 h2
    __half2* sA   = smem + 36864;         // 64*128 h2 (one 64x256 fp16 panel)
    float*   sPre = (float*)(smem + 36864 + 8192);  // [3][64][24]
    float*   sRed = sPre + 4608;          // [64][24]
    float*   sH0f = sRed + 1536;          // [64][8]
    float*   sH1f = sH0f + 512;
    float*   sBias = sH1f + 512;          // [3][24]

    const int tid = threadIdx.x, wid = tid >> 5, lane = tid & 31;
    const int mt = wid & 3, kh = wid >> 2, gID = lane >> 2, tg = lane & 3;
    const int j0 = blockIdx.x * 8;
    const int b = tid >> 2, jj = (tid & 3) * 2;
    const int swz = gID << 2;

    // persistent weight slices: rows {g*1024 + j0 + j} of each matrix
    const float* Wm[3] = {Whh0, Wih1, Whh1};
    for (int m = 0; m < 3; m++) {
        const float4* W4 = (const float4*)Wm[m];
        for (int i = tid; i < 24 * 256; i += 256) {
            int r = i >> 8, cu = i & 255;
            int grow = (r >> 3) * NH + j0 + (r & 7);
            float4 v = W4[grow * 256 + cu];
            int base = (cu * 2) ^ ((r & 7) << 2);
            __half2* d = &sW[m * 12288 + r * 512 + base];
            d[0] = __floats2half2_rn(v.x, v.y);
            d[1] = __floats2half2_rn(v.z, v.w);
        }
    }
    const float* Bm[3] = {bhh0, bih1, bhh1};
    if (tid < 72) {
        int m = tid / 24, r = tid % 24;
        sBias[tid] = Bm[m][(r >> 3) * NH + j0 + (r & 7)];
    }
    {   // init hidden from encoder_h, publish fp16 copies
        float a = encH[b * NH + j0 + jj], c2 = encH[b * NH + j0 + jj + 1];
        sH0f[b * 8 + jj] = a; sH0f[b * 8 + jj + 1] = c2;
        sH1f[b * 8 + jj] = a; sH1f[b * 8 + jj + 1] = c2;
        __half2 hp = __floats2half2_rn(a, c2);
        g_h0[0][b * 512 + ((j0 + jj) >> 1)] = hp;
        g_h1[0][b * 512 + ((j0 + jj) >> 1)] = hp;
    }
    unsigned tgt = GCTA;
    grid_barrier(tgt);

    auto do_gemm = [&](const uint4* A4, int mat, float* dst) {
        float c[3][4] = {};
        for (int p = 0; p < 4; p++) {
            __syncthreads();
#pragma unroll
            for (int q = 0; q < 8; q++) {
                int idx = q * 256 + tid, r = idx >> 5, cu = idx & 31;
                uint4 v = A4[r * 128 + p * 32 + cu];
                int base = (cu * 4) ^ ((r & 7) << 2);
                *(uint4*)&sA[r * 128 + base] = v;
            }
            __syncthreads();
            if ((p >> 1) == kh) {
                int ra0 = (mt * 16 + gID) * 128, ra1 = ra0 + 8 * 128;
#pragma unroll 4
                for (int ks = 0; ks < 16; ks++) {
                    int col = ks * 8 + tg;
                    unsigned a0 = *(const unsigned*)&sA[ra0 + (col ^ swz)];
                    unsigned a1 = *(const unsigned*)&sA[ra1 + (col ^ swz)];
                    unsigned a2 = *(const unsigned*)&sA[ra0 + ((col + 4) ^ swz)];
                    unsigned a3 = *(const unsigned*)&sA[ra1 + ((col + 4) ^ swz)];
                    int gk8 = (p * 16 + ks) * 8 + tg;
#pragma unroll
                    for (int g = 0; g < 3; g++) {
                        const __half2* bw = &sW[mat * 12288 + (g * 8 + gID) * 512];
                        unsigned b0 = *(const unsigned*)&bw[gk8 ^ swz];
                        unsigned b1 = *(const unsigned*)&bw[(gk8 + 4) ^ swz];
                        mma16816(c[g], a0, a1, a2, a3, b0, b1);
                    }
                }
            }
        }
        __syncthreads();
        int m0r = mt * 16 + gID, nc = 2 * tg;
        if (kh == 1) {
#pragma unroll
            for (int g = 0; g < 3; g++) {
                *(float2*)&sRed[m0r * 24 + g * 8 + nc]       = make_float2(c[g][0], c[g][1]);
                *(float2*)&sRed[(m0r + 8) * 24 + g * 8 + nc] = make_float2(c[g][2], c[g][3]);
            }
        }
        __syncthreads();
        if (kh == 0) {
#pragma unroll
            for (int g = 0; g < 3; g++) {
                float2 r0 = *(float2*)&sRed[m0r * 24 + g * 8 + nc];
                float2 r1 = *(float2*)&sRed[(m0r + 8) * 24 + g * 8 + nc];
                *(float2*)&dst[m0r * 24 + g * 8 + nc]       = make_float2(c[g][0] + r0.x, c[g][1] + r0.y);
                *(float2*)&dst[(m0r + 8) * 24 + g * 8 + nc] = make_float2(c[g][2] + r1.x, c[g][3] + r1.y);
            }
        }
        __syncthreads();
    };

    for (int t = 0; t < NT; t++) {
        int cur = t & 1, nxt = cur ^ 1;
        do_gemm((const uint4*)g_h0[cur], 0, sPre);            // gh0 (old h0)
        do_gemm((const uint4*)g_h1[cur], 2, sPre + 2 * 1536); // gh1 (old h1)

        // layer-0 elementwise
        {
            size_t gi = ((size_t)t * NB + b) * 1536 + ((j0 + jj) >> 1);
            __half2 hr = g_gi0[gi], hz = g_gi0[gi + 512], hn = g_gi0[gi + 1024];
            float gir[2] = {__low2float(hr), __high2float(hr)};
            float giz[2] = {__low2float(hz), __high2float(hz)};
            float gin[2] = {__low2float(hn), __high2float(hn)};
            float h0n[2];
#pragma unroll
            for (int d = 0; d < 2; d++) {
                int j = jj + d;
                float ghr = sPre[b * 24 + j]      + sBias[j];
                float ghz = sPre[b * 24 + 8 + j]  + sBias[8 + j];
                float ghn = sPre[b * 24 + 16 + j] + sBias[16 + j];
                float r = sigm(gir[d] + ghr);
                float z = sigm(giz[d] + ghz);
                float n = tanhf(gin[d] + r * ghn);
                h0n[d] = (1.0f - z) * n + z * sH0f[b * 8 + j];
            }
            sH0f[b * 8 + jj] = h0n[0]; sH0f[b * 8 + jj + 1] = h0n[1];
            g_h0[nxt][b * 512 + ((j0 + jj) >> 1)] = __floats2half2_rn(h0n[0], h0n[1]);
        }
        grid_barrier(tgt);   // h0_new visible everywhere

        do_gemm((const uint4*)g_h0[nxt], 1, sPre + 1536);     // gi1 (new h0)

        // layer-1 elementwise + output
        {
            float h1n[2];
#pragma unroll
            for (int d = 0; d < 2; d++) {
                int j = jj + d;
                float gir1 = sPre[1536 + b * 24 + j]      + sBias[24 + j];
                float giz1 = sPre[1536 + b * 24 + 8 + j]  + sBias[32 + j];
                float gin1 = sPre[1536 + b * 24 + 16 + j] + sBias[40 + j];
                float ghr1 = sPre[3072 + b * 24 + j]      + sBias[48 + j];
                float ghz1 = sPre[3072 + b * 24 + 8 + j]  + sBias[56 + j];
                float ghn1 = sPre[3072 + b * 24 + 16 + j] + sBias[64 + j];
                float r = sigm(gir1 + ghr1);
                float z = sigm(giz1 + ghz1);
                float n = tanhf(gin1 + r * ghn1);
                h1n[d] = (1.0f - z) * n + z * sH1f[b * 8 + j];
            }
            sH1f[b * 8 + jj] = h1n[0]; sH1f[b * 8 + jj + 1] = h1n[1];
            g_h1[nxt][b * 512 + ((j0 + jj) >> 1)] = __floats2half2_rn(h1n[0], h1n[1]);
            *(float2*)&out[((size_t)b * NT + t) * NH + j0 + jj] = make_float2(h1n[0], h1n[1]);
            if (hasFinal && t == NT - 1) {
                float* o2 = out + (size_t)NB * NT * NH;
                *(float2*)&o2[b * NH + j0 + jj] = make_float2(h1n[0], h1n[1]);
            }
        }
        grid_barrier(tgt);   // h1_new visible everywhere
    }
}

extern "C" void kernel_launch(void* const* d_in, const int* in_sizes, int n_in,
                              void* d_out, int out_size) {
    const float* x    = (const float*)d_in[0];
    const float* encH = (const float*)d_in[2];
    const float* Wih0 = (const float*)d_in[3];
    const float* Whh0 = (const float*)d_in[4];
    const float* bih0 = (const float*)d_in[5];
    const float* bhh0 = (const float*)d_in[6];
    const float* Wih1 = (const float*)d_in[7];
    const float* Whh1 = (const float*)d_in[8];
    const float* bih1 = (const float*)d_in[9];
    const float* bhh1 = (const float*)d_in[10];
    float* out = (float*)d_out;
    int hasFinal = (out_size >= NB * NT * NH + NB * NH) ? 1 : 0;

    cudaFuncSetAttribute(k_gru, cudaFuncAttributeMaxDynamicSharedMemorySize, SMEM_BYTES);

    k_cvt_x<<<16384, 256>>>((const float4*)x);
    k_cvt_w<<<1536, 256>>>((const float4*)Wih0);
    dim3 g1(48, 512);
    k_gi0<<<g1, 256>>>(bih0);
    k_gru<<<GCTA, 256, SMEM_BYTES>>>(out, Whh0, Wih1, Whh1,
                                     bhh0, bih1, bhh1, encH, hasFinal);
}

// round 5
// speedup vs baseline: 1.6930x; 1.6930x over previous
#include <cuda_runtime.h>
#include <cuda_fp16.h>
#include <math.h>

#define NB   64
#define NT   512
#define NIN  512
#define NH   1024
#define NH3  3072
#define GCTA 128

__device__ __half2  g_x16[NB * NT * NIN / 2];
__device__ __half2  g_w16[NH3 * NIN / 2];
__device__ __half2  g_gi0[(size_t)NB * NT * NH3 / 2];  // [t][b][3072] fp16, +bias
__device__ __half2  g_h0[2][NB * NH / 2];
__device__ __half2  g_h1[2][NB * NH / 2];
__device__ unsigned g_bar;

__device__ __forceinline__ float sigm(float x) { return 1.0f / (1.0f + __expf(-x)); }

__device__ __forceinline__ void mma16816(float* c, unsigned a0, unsigned a1,
                                         unsigned a2, unsigned a3,
                                         unsigned b0, unsigned b1) {
    asm volatile(
        "mma.sync.aligned.m16n8k16.row.col.f32.f16.f16.f32 "
        "{%0,%1,%2,%3},{%4,%5,%6,%7},{%8,%9},{%0,%1,%2,%3};\n"
        : "+f"(c[0]), "+f"(c[1]), "+f"(c[2]), "+f"(c[3])
        : "r"(a0), "r"(a1), "r"(a2), "r"(a3), "r"(b0), "r"(b1));
}

__device__ __forceinline__ void grid_barrier(unsigned& target) {
    __syncthreads();
    if (threadIdx.x == 0) {
        __threadfence();
        atomicAdd(&g_bar, 1u);
        unsigned v;
        do {
            asm volatile("ld.global.acquire.gpu.u32 %0, [%1];"
                         : "=r"(v) : "l"(&g_bar) : "memory");
        } while (v < target);
    }
    __syncthreads();
    target += GCTA;
}

__global__ void k_cvt_x(const float4* __restrict__ x) {
    int i = blockIdx.x * 256 + threadIdx.x;
    if (i == 0) g_bar = 0;
    float4 v = x[i];
    g_x16[i * 2]     = __floats2half2_rn(v.x, v.y);
    g_x16[i * 2 + 1] = __floats2half2_rn(v.z, v.w);
}
__global__ void k_cvt_w(const float4* __restrict__ w) {
    int i = blockIdx.x * 256 + threadIdx.x;
    float4 v = w[i];
    g_w16[i * 2]     = __floats2half2_rn(v.x, v.y);
    g_w16[i * 2 + 1] = __floats2half2_rn(v.z, v.w);
}

// ---- phase A: gi0 = x @ Wih0^T + bih0 ----
__global__ void __launch_bounds__(256) k_gi0(const float* __restrict__ bih0) {
    __shared__ __half2 sA[64 * 32];
    __shared__ __half2 sB[64 * 32];
    const int tid = threadIdx.x, wid = tid >> 5, lane = tid & 31;
    const int wm = wid & 3, wn = wid >> 2, gID = lane >> 2, tg = lane & 3;
    const int m0 = blockIdx.y * 64, n0 = blockIdx.x * 64;
    const uint4* A4 = (const uint4*)g_x16;
    const uint4* B4 = (const uint4*)g_w16;
    const int swz = gID << 2;
    float c[4][4] = {};

    for (int p = 0; p < 8; p++) {
        __syncthreads();
#pragma unroll
        for (int rep = 0; rep < 2; rep++) {
            int idx = rep * 256 + tid, r = idx >> 3, cu = idx & 7;
            int base = (cu * 4) ^ ((r & 7) << 2);
            *(uint4*)&sA[r * 32 + base] = A4[(m0 + r) * 64 + p * 8 + cu];
            *(uint4*)&sB[r * 32 + base] = B4[(n0 + r) * 64 + p * 8 + cu];
        }
        __syncthreads();
#pragma unroll
        for (int ks = 0; ks < 4; ks++) {
            int col = ks * 8 + tg;
            int ra0 = (wm * 16 + gID) * 32, ra1 = ra0 + 8 * 32;
            unsigned a0 = *(const unsigned*)&sA[ra0 + (col ^ swz)];
            unsigned a1 = *(const unsigned*)&sA[ra1 + (col ^ swz)];
            unsigned a2 = *(const unsigned*)&sA[ra0 + ((col + 4) ^ swz)];
            unsigned a3 = *(const unsigned*)&sA[ra1 + ((col + 4) ^ swz)];
#pragma unroll
            for (int nt = 0; nt < 4; nt++) {
                int rb = (wn * 32 + nt * 8 + gID) * 32;
                unsigned b0 = *(const unsigned*)&sB[rb + (col ^ swz)];
                unsigned b1 = *(const unsigned*)&sB[rb + ((col + 4) ^ swz)];
                mma16816(c[nt], a0, a1, a2, a3, b0, b1);
            }
        }
    }
    int mrow = m0 + wm * 16 + gID;
#pragma unroll
    for (int nt = 0; nt < 4; nt++) {
        int nc = n0 + wn * 32 + nt * 8 + tg * 2;
        float b0 = bih0[nc], b1 = bih0[nc + 1];
        int bA = mrow >> 9, tA = mrow & 511;
        g_gi0[((size_t)tA * NB + bA) * 1536 + (nc >> 1)] =
            __floats2half2_rn(c[nt][0] + b0, c[nt][1] + b1);
        int m2 = mrow + 8, bB = m2 >> 9, tB = m2 & 511;
        g_gi0[((size_t)tB * NB + bB) * 1536 + (nc >> 1)] =
            __floats2half2_rn(c[nt][2] + b0, c[nt][3] + b1);
    }
}

// ---- persistent recurrence: layer-1 lags layer-0 by one step; 1 barrier/iter
// smem: sW 3*24*512 h2 | sA 2*(64*64) h2 | sPre [3][64][24]f | sRed [64][24]f
//       sH0f/sH1f [64][8]f | sBias [72]f
#define SMEM_BYTES ((36864 + 8192) * 4 + (4608 + 1536 + 512 + 512 + 72) * 4)

__global__ void __launch_bounds__(256, 1) k_gru(
    float* __restrict__ out,
    const float* __restrict__ Whh0, const float* __restrict__ Wih1,
    const float* __restrict__ Whh1,
    const float* __restrict__ bhh0, const float* __restrict__ bih1,
    const float* __restrict__ bhh1,
    const float* __restrict__ encH, int hasFinal) {
    extern __shared__ __align__(16) __half2 smem[];
    __half2* sW   = smem;                  // 36864 h2
    __half2* sA   = smem + 36864;          // 2 x 4096 h2 (64x128 fp16 panels)
    float*   sPre = (float*)(smem + 36864 + 8192);
    float*   sRed = sPre + 4608;
    float*   sH0f = sRed + 1536;
    float*   sH1f = sH0f + 512;
    float*   sBias = sH1f + 512;

    const int tid = threadIdx.x, wid = tid >> 5, lane = tid & 31;
    const int mt = wid & 3, ng = wid >> 2, gID = lane >> 2, tg = lane & 3;
    const int j0 = blockIdx.x * 8;
    const int b = tid >> 2, jj = (tid & 3) * 2;
    const int swz = gID << 2;
    const int lr = tid >> 4, lc = tid & 15;          // panel loader: 4 rows apart
    const int lbase = (lc * 4) ^ ((lr & 7) << 2);

    const float* Wm[3] = {Whh0, Wih1, Whh1};
    for (int m = 0; m < 3; m++) {
        const float4* W4 = (const float4*)Wm[m];
        for (int i = tid; i < 24 * 256; i += 256) {
            int r = i >> 8, cu = i & 255;
            int grow = (r >> 3) * NH + j0 + (r & 7);
            float4 v = W4[grow * 256 + cu];
            int base = (cu * 2) ^ ((r & 7) << 2);
            __half2* d = &sW[m * 12288 + r * 512 + base];
            d[0] = __floats2half2_rn(v.x, v.y);
            d[1] = __floats2half2_rn(v.z, v.w);
        }
    }
    const float* Bm[3] = {bhh0, bih1, bhh1};
    if (tid < 72) {
        int m = tid / 24, r = tid % 24;
        sBias[tid] = Bm[m][(r >> 3) * NH + j0 + (r & 7)];
    }
    {
        float a = encH[b * NH + j0 + jj], c2 = encH[b * NH + j0 + jj + 1];
        sH0f[b * 8 + jj] = a; sH0f[b * 8 + jj + 1] = c2;
        sH1f[b * 8 + jj] = a; sH1f[b * 8 + jj + 1] = c2;
        __half2 hp = __floats2half2_rn(a, c2);
        g_h0[1][b * 512 + ((j0 + jj) >> 1)] = hp;   // h0^{-1}
        g_h1[0][b * 512 + ((j0 + jj) >> 1)] = hp;   // h1^{-1}
    }
    unsigned tgt = GCTA;
    grid_barrier(tgt);

    for (int i = 0; i <= NT; i++) {
        const int rb = (i + 1) & 1, wb = i & 1;
        const uint4* A1 = (const uint4*)g_h0[rb];   // h0^{i-1}
        const uint4* A2 = (const uint4*)g_h1[rb];   // h1^{i-2}
        const int NP = (i == 0) ? 8 : 16;

        // prefetch gi0(t=i) for this thread's slice
        __half2 pg0, pg1, pg2;
        if (i < NT) {
            size_t gi = ((size_t)i * NB + b) * 1536 + ((j0 + jj) >> 1);
            pg0 = g_gi0[gi]; pg1 = g_gi0[gi + 512]; pg2 = g_gi0[gi + 1024];
        }

        float cA[3][4] = {}, cB[3][4] = {};
        uint4 stg[4];
        // prologue: panel 0 of A1
#pragma unroll
        for (int q = 0; q < 4; q++) stg[q] = A1[(lr + q * 16) * 128 + lc];
#pragma unroll
        for (int q = 0; q < 4; q++)
            *(uint4*)&sA[(lr + q * 16) * 64 + lbase] = stg[q];
        __syncthreads();

        for (int pp = 0; pp < NP; pp++) {
            if (pp + 1 < NP) {      // issue next panel's loads (overlap w/ MMA)
                const uint4* Ax = (pp + 1 < 8) ? A1 : A2;
                int p = (pp + 1) & 7;
#pragma unroll
                for (int q = 0; q < 4; q++)
                    stg[q] = Ax[(lr + q * 16) * 128 + p * 16 + lc];
            }
            const __half2* sAb = sA + (pp & 1) * 4096;
            const int ra0 = (mt * 16 + gID) * 64, ra1 = ra0 + 8 * 64;
            if (pp < 8) {           // A1: ng picks weight matrix (mat0 / mat1)
                const __half2* bw0 = &sW[ng * 12288 + gID * 512];
#pragma unroll
                for (int ks = 0; ks < 8; ks++) {
                    int col = ks * 8 + tg;
                    unsigned a0 = *(const unsigned*)&sAb[ra0 + (col ^ swz)];
                    unsigned a1 = *(const unsigned*)&sAb[ra1 + (col ^ swz)];
                    unsigned a2 = *(const unsigned*)&sAb[ra0 + ((col + 4) ^ swz)];
                    unsigned a3 = *(const unsigned*)&sAb[ra1 + ((col + 4) ^ swz)];
                    int gk8 = (pp * 8 + ks) * 8 + tg;
#pragma unroll
                    for (int g = 0; g < 3; g++) {
                        unsigned b0 = *(const unsigned*)&bw0[g * 8 * 512 + (gk8 ^ swz)];
                        unsigned b1 = *(const unsigned*)&bw0[g * 8 * 512 + ((gk8 + 4) ^ swz)];
                        mma16816(cA[g], a0, a1, a2, a3, b0, b1);
                    }
                }
            } else {                // A2: mat2, K-split by ng within panel
                const __half2* bw2 = &sW[2 * 12288 + gID * 512];
                int p = pp & 7;
#pragma unroll
                for (int ks2 = 0; ks2 < 4; ks2++) {
                    int ks = ng * 4 + ks2;
                    int col = ks * 8 + tg;
                    unsigned a0 = *(const unsigned*)&sAb[ra0 + (col ^ swz)];
                    unsigned a1 = *(const unsigned*)&sAb[ra1 + (col ^ swz)];
                    unsigned a2 = *(const unsigned*)&sAb[ra0 + ((col + 4) ^ swz)];
                    unsigned a3 = *(const unsigned*)&sAb[ra1 + ((col + 4) ^ swz)];
                    int gk8 = (p * 8 + ks) * 8 + tg;
#pragma unroll
                    for (int g = 0; g < 3; g++) {
                        unsigned b0 = *(const unsigned*)&bw2[g * 8 * 512 + (gk8 ^ swz)];
                        unsigned b1 = *(const unsigned*)&bw2[g * 8 * 512 + ((gk8 + 4) ^ swz)];
                        mma16816(cB[g], a0, a1, a2, a3, b0, b1);
                    }
                }
            }
            if (pp + 1 < NP) {
#pragma unroll
                for (int q = 0; q < 4; q++)
                    *(uint4*)&sA[((pp + 1) & 1) * 4096 + (lr + q * 16) * 64 + lbase] = stg[q];
            }
            __syncthreads();
        }

        // epilogue: assemble sPre[0]=gh0, sPre[1]=gi1, sPre[2]=gh1
        int m0r = mt * 16 + gID, nc = 2 * tg;
        if (ng == 1) {
#pragma unroll
            for (int g = 0; g < 3; g++) {
                *(float2*)&sPre[1536 + m0r * 24 + g * 8 + nc]       = make_float2(cA[g][0], cA[g][1]);
                *(float2*)&sPre[1536 + (m0r + 8) * 24 + g * 8 + nc] = make_float2(cA[g][2], cA[g][3]);
                *(float2*)&sRed[m0r * 24 + g * 8 + nc]       = make_float2(cB[g][0], cB[g][1]);
                *(float2*)&sRed[(m0r + 8) * 24 + g * 8 + nc] = make_float2(cB[g][2], cB[g][3]);
            }
        }
        __syncthreads();
        if (ng == 0) {
#pragma unroll
            for (int g = 0; g < 3; g++) {
                *(float2*)&sPre[m0r * 24 + g * 8 + nc]       = make_float2(cA[g][0], cA[g][1]);
                *(float2*)&sPre[(m0r + 8) * 24 + g * 8 + nc] = make_float2(cA[g][2], cA[g][3]);
                float2 r0 = *(float2*)&sRed[m0r * 24 + g * 8 + nc];
                float2 r1 = *(float2*)&sRed[(m0r + 8) * 24 + g * 8 + nc];
                *(float2*)&sPre[3072 + m0r * 24 + g * 8 + nc]       = make_float2(cB[g][0] + r0.x, cB[g][1] + r0.y);
                *(float2*)&sPre[3072 + (m0r + 8) * 24 + g * 8 + nc] = make_float2(cB[g][2] + r1.x, cB[g][3] + r1.y);
            }
        }
        __syncthreads();

        if (i < NT) {   // layer-0 step i
            float gir[2] = {__low2float(pg0), __high2float(pg0)};
            float giz[2] = {__low2float(pg1), __high2float(pg1)};
            float gin[2] = {__low2float(pg2), __high2float(pg2)};
            float h0n[2];
#pragma unroll
            for (int d = 0; d < 2; d++) {
                int j = jj + d;
                float r = sigm(gir[d] + sPre[b * 24 + j]      + sBias[j]);
                float z = sigm(giz[d] + sPre[b * 24 + 8 + j]  + sBias[8 + j]);
                float n = tanhf(gin[d] + r * (sPre[b * 24 + 16 + j] + sBias[16 + j]));
                h0n[d] = (1.0f - z) * n + z * sH0f[b * 8 + j];
            }
            sH0f[b * 8 + jj] = h0n[0]; sH0f[b * 8 + jj + 1] = h0n[1];
            g_h0[wb][b * 512 + ((j0 + jj) >> 1)] = __floats2half2_rn(h0n[0], h0n[1]);
        }
        if (i > 0) {    // layer-1 step i-1
            float h1n[2];
#pragma unroll
            for (int d = 0; d < 2; d++) {
                int j = jj + d;
                float r = sigm(sPre[1536 + b * 24 + j]     + sBias[24 + j] +
                               sPre[3072 + b * 24 + j]     + sBias[48 + j]);
                float z = sigm(sPre[1536 + b * 24 + 8 + j] + sBias[32 + j] +
                               sPre[3072 + b * 24 + 8 + j] + sBias[56 + j]);
                float n = tanhf(sPre[1536 + b * 24 + 16 + j] + sBias[40 + j] +
                                r * (sPre[3072 + b * 24 + 16 + j] + sBias[64 + j]));
                h1n[d] = (1.0f - z) * n + z * sH1f[b * 8 + j];
            }
            sH1f[b * 8 + jj] = h1n[0]; sH1f[b * 8 + jj + 1] = h1n[1];
            g_h1[wb][b * 512 + ((j0 + jj) >> 1)] = __floats2half2_rn(h1n[0], h1n[1]);
            int t = i - 1;
            *(float2*)&out[((size_t)b * NT + t) * NH + j0 + jj] = make_float2(h1n[0], h1n[1]);
            if (hasFinal && i == NT) {
                float* o2 = out + (size_t)NB * NT * NH;
                *(float2*)&o2[b * NH + j0 + jj] = make_float2(h1n[0], h1n[1]);
            }
        }
        grid_barrier(tgt);
    }
}

extern "C" void kernel_launch(void* const* d_in, const int* in_sizes, int n_in,
                              void* d_out, int out_size) {
    const float* x    = (const float*)d_in[0];
    const float* encH = (const float*)d_in[2];
    const float* Wih0 = (const float*)d_in[3];
    const float* Whh0 = (const float*)d_in[4];
    const float* bih0 = (const float*)d_in[5];
    const float* bhh0 = (const float*)d_in[6];
    const float* Wih1 = (const float*)d_in[7];
    const float* Whh1 = (const float*)d_in[8];
    const float* bih1 = (const float*)d_in[9];
    const float* bhh1 = (const float*)d_in[10];
    float* out = (float*)d_out;
    int hasFinal = (out_size >= NB * NT * NH + NB * NH) ? 1 : 0;

    cudaFuncSetAttribute(k_gru, cudaFuncAttributeMaxDynamicSharedMemorySize, SMEM_BYTES);

    k_cvt_x<<<16384, 256>>>((const float4*)x);
    k_cvt_w<<<1536, 256>>>((const float4*)Wih0);
    dim3 g1(48, 512);
    k_gi0<<<g1, 256>>>(bih0);
    k_gru<<<GCTA, 256, SMEM_BYTES>>>(out, Whh0, Wih1, Whh1,
                                     bhh0, bih1, bhh1, encH, hasFinal);
}

// round 6
// speedup vs baseline: 1.7326x; 1.0234x over previous
#include <cuda_runtime.h>
#include <cuda_fp16.h>
#include <math.h>

#define NB   64
#define NT   512
#define NIN  512
#define NH   1024
#define NH3  3072
#define GCTA 128

__device__ __half2  g_x16[NB * NT * NIN / 2];
__device__ __half2  g_w16[NH3 * NIN / 2];
__device__ __half2  g_gi0[(size_t)NB * NT * NH3 / 2];  // [t][b][3072] fp16, +bias
__device__ __half2  g_h0[2][NB * NH / 2];
__device__ __half2  g_h1[2][NB * NH / 2];
__device__ unsigned g_bar0, g_bar1, g_bari;

__device__ __forceinline__ float sigm(float x) { return 1.0f / (1.0f + __expf(-x)); }

__device__ __forceinline__ void mma16816(float* c, unsigned a0, unsigned a1,
                                         unsigned a2, unsigned a3,
                                         unsigned b0, unsigned b1) {
    asm volatile(
        "mma.sync.aligned.m16n8k16.row.col.f32.f16.f16.f32 "
        "{%0,%1,%2,%3},{%4,%5,%6,%7},{%8,%9},{%0,%1,%2,%3};\n"
        : "+f"(c[0]), "+f"(c[1]), "+f"(c[2]), "+f"(c[3])
        : "r"(a0), "r"(a1), "r"(a2), "r"(a3), "r"(b0), "r"(b1));
}

__device__ __forceinline__ void cp16(unsigned dst, const void* src) {
    asm volatile("cp.async.cg.shared.global [%0], [%1], 16;" :: "r"(dst), "l"(src));
}
__device__ __forceinline__ void cp_commit() {
    asm volatile("cp.async.commit_group;");
}
template <int N> __device__ __forceinline__ void cp_wait() {
    asm volatile("cp.async.wait_group %0;" :: "n"(N));
}

__device__ __forceinline__ void bar_arrive(unsigned* bar) {
    __syncthreads();
    if (threadIdx.x == 0) { __threadfence(); atomicAdd(bar, 1u); }
}
__device__ __forceinline__ void bar_wait(unsigned* bar, unsigned target) {
    if (threadIdx.x == 0) {
        unsigned v;
        do {
            asm volatile("ld.global.acquire.gpu.u32 %0, [%1];"
                         : "=r"(v) : "l"(bar) : "memory");
        } while (v < target);
    }
    __syncthreads();
}

__global__ void k_cvt_x(const float4* __restrict__ x) {
    int i = blockIdx.x * 256 + threadIdx.x;
    if (i == 0) { g_bar0 = 0; g_bar1 = 0; g_bari = 0; }
    float4 v = x[i];
    g_x16[i * 2]     = __floats2half2_rn(v.x, v.y);
    g_x16[i * 2 + 1] = __floats2half2_rn(v.z, v.w);
}
__global__ void k_cvt_w(const float4* __restrict__ w) {
    int i = blockIdx.x * 256 + threadIdx.x;
    float4 v = w[i];
    g_w16[i * 2]     = __floats2half2_rn(v.x, v.y);
    g_w16[i * 2 + 1] = __floats2half2_rn(v.z, v.w);
}

// ---- phase A: gi0 = x @ Wih0^T + bih0 ----
__global__ void __launch_bounds__(256) k_gi0(const float* __restrict__ bih0) {
    __shared__ __half2 sA[64 * 32];
    __shared__ __half2 sB[64 * 32];
    const int tid = threadIdx.x, wid = tid >> 5, lane = tid & 31;
    const int wm = wid & 3, wn = wid >> 2, gID = lane >> 2, tg = lane & 3;
    const int m0 = blockIdx.y * 64, n0 = blockIdx.x * 64;
    const uint4* A4 = (const uint4*)g_x16;
    const uint4* B4 = (const uint4*)g_w16;
    const int swz = gID << 2;
    float c[4][4] = {};

    for (int p = 0; p < 8; p++) {
        __syncthreads();
#pragma unroll
        for (int rep = 0; rep < 2; rep++) {
            int idx = rep * 256 + tid, r = idx >> 3, cu = idx & 7;
            int base = (cu * 4) ^ ((r & 7) << 2);
            *(uint4*)&sA[r * 32 + base] = A4[(m0 + r) * 64 + p * 8 + cu];
            *(uint4*)&sB[r * 32 + base] = B4[(n0 + r) * 64 + p * 8 + cu];
        }
        __syncthreads();
#pragma unroll
        for (int ks = 0; ks < 4; ks++) {
            int col = ks * 8 + tg;
            int ra0 = (wm * 16 + gID) * 32, ra1 = ra0 + 8 * 32;
            unsigned a0 = *(const unsigned*)&sA[ra0 + (col ^ swz)];
            unsigned a1 = *(const unsigned*)&sA[ra1 + (col ^ swz)];
            unsigned a2 = *(const unsigned*)&sA[ra0 + ((col + 4) ^ swz)];
            unsigned a3 = *(const unsigned*)&sA[ra1 + ((col + 4) ^ swz)];
#pragma unroll
            for (int nt = 0; nt < 4; nt++) {
                int rb = (wn * 32 + nt * 8 + gID) * 32;
                unsigned b0 = *(const unsigned*)&sB[rb + (col ^ swz)];
                unsigned b1 = *(const unsigned*)&sB[rb + ((col + 4) ^ swz)];
                mma16816(c[nt], a0, a1, a2, a3, b0, b1);
            }
        }
    }
    int mrow = m0 + wm * 16 + gID;
#pragma unroll
    for (int nt = 0; nt < 4; nt++) {
        int nc = n0 + wn * 32 + nt * 8 + tg * 2;
        float b0 = bih0[nc], b1 = bih0[nc + 1];
        int bA = mrow >> 9, tA = mrow & 511;
        g_gi0[((size_t)tA * NB + bA) * 1536 + (nc >> 1)] =
            __floats2half2_rn(c[nt][0] + b0, c[nt][1] + b1);
        int m2 = mrow + 8, bB = m2 >> 9, tB = m2 & 511;
        g_gi0[((size_t)tB * NB + bB) * 1536 + (nc >> 1)] =
            __floats2half2_rn(c[nt][2] + b0, c[nt][3] + b1);
    }
}

// ---- persistent recurrence: L1 lags L0 by 2 steps; both barriers hidden ----
// smem: sW 3*24*512 h2 | sA 3*(64*64) h2 | sPre [3][64][24]f | sRed [64][24]f
#define SMEM_BYTES ((36864 + 12288) * 4 + (4608 + 1536 + 512 + 512 + 72) * 4)

__global__ void __launch_bounds__(256, 1) k_gru(
    float* __restrict__ out,
    const float* __restrict__ Whh0, const float* __restrict__ Wih1,
    const float* __restrict__ Whh1,
    const float* __restrict__ bhh0, const float* __restrict__ bih1,
    const float* __restrict__ bhh1,
    const float* __restrict__ encH, int hasFinal) {
    extern __shared__ __align__(16) __half2 smem[];
    __half2* sW   = smem;                  // 36864 h2
    __half2* sA   = smem + 36864;          // 3 x 4096 h2 (64x128 fp16 panels)
    float*   sPre = (float*)(smem + 36864 + 12288);  // [3][64][24]; slot1=gi1 persists
    float*   sRed = sPre + 4608;
    float*   sH0f = sRed + 1536;
    float*   sH1f = sH0f + 512;
    float*   sBias = sH1f + 512;

    const int tid = threadIdx.x, wid = tid >> 5, lane = tid & 31;
    const int mt = wid & 3, ng = wid >> 2, gID = lane >> 2, tg = lane & 3;
    const int j0 = blockIdx.x * 8;
    const int b = tid >> 2, jj = (tid & 3) * 2;
    const int swz = gID << 2;
    const int lr = tid >> 4, lc = tid & 15;
    const int lbase = (lc * 4) ^ ((lr & 7) << 2);
    const unsigned sAu = (unsigned)__cvta_generic_to_shared(sA);

    const float* Wm[3] = {Whh0, Wih1, Whh1};
    for (int m = 0; m < 3; m++) {
        const float4* W4 = (const float4*)Wm[m];
        for (int i = tid; i < 24 * 256; i += 256) {
            int r = i >> 8, cu = i & 255;
            int grow = (r >> 3) * NH + j0 + (r & 7);
            float4 v = W4[grow * 256 + cu];
            int base = (cu * 2) ^ ((r & 7) << 2);
            __half2* d = &sW[m * 12288 + r * 512 + base];
            d[0] = __floats2half2_rn(v.x, v.y);
            d[1] = __floats2half2_rn(v.z, v.w);
        }
    }
    const float* Bm[3] = {bhh0, bih1, bhh1};
    if (tid < 72) {
        int m = tid / 24, r = tid % 24;
        sBias[tid] = Bm[m][(r >> 3) * NH + j0 + (r & 7)];
    }
    {
        float a = encH[b * NH + j0 + jj], c2 = encH[b * NH + j0 + jj + 1];
        sH0f[b * 8 + jj] = a; sH0f[b * 8 + jj + 1] = c2;
        sH1f[b * 8 + jj] = a; sH1f[b * 8 + jj + 1] = c2;
        __half2 hp = __floats2half2_rn(a, c2);
        g_h0[1][b * 512 + ((j0 + jj) >> 1)] = hp;   // h0^{-1}
        g_h1[1][b * 512 + ((j0 + jj) >> 1)] = hp;   // h1^{-1}
    }
    // one full init barrier
    bar_arrive(&g_bari);
    bar_wait(&g_bari, GCTA);

    auto issue_panel = [&](const uint4* A4, int p, int buf) {
#pragma unroll
        for (int q = 0; q < 4; q++)
            cp16(sAu + (unsigned)((buf * 4096 + (lr + q * 16) * 64 + lbase) * 4),
                 A4 + (size_t)(lr + q * 16) * 128 + p * 16 + lc);
        cp_commit();
    };

    for (int i = 0; i <= NT + 1; i++) {
        // prefetch gi0(t=i) early (used in phase 5)
        __half2 pg0, pg1, pg2;
        if (i < NT) {
            size_t gi = ((size_t)i * NB + b) * 1536 + ((j0 + jj) >> 1);
            pg0 = g_gi0[gi]; pg1 = g_gi0[gi + 512]; pg2 = g_gi0[gi + 1024];
        }

        // ---- phase 1: wait bar1 (h1^{i-3} visible) ----
        if (i >= 3) bar_wait(&g_bar1, (unsigned)(i - 2) * GCTA);

        // ---- phase 2: A2 GEMM: gh1 = Whh1 @ h1^{i-3} ----
        if (i >= 2) {
            const uint4* A2 = (const uint4*)g_h1[(i + 1) & 1];  // (i-3)&1
            float cB[3][4] = {};
            issue_panel(A2, 0, 0);
            issue_panel(A2, 1, 1);
            for (int p = 0; p < 8; p++) {
                if (p < 7) cp_wait<1>(); else cp_wait<0>();
                __syncthreads();
                if (p + 2 < 8) issue_panel(A2, p + 2, (p + 2) % 3);
                const __half2* sAb = sA + (p % 3) * 4096;
                const int ra0 = (mt * 16 + gID) * 64, ra1 = ra0 + 512;
                const __half2* bw2 = &sW[2 * 12288 + gID * 512];
#pragma unroll
                for (int ks2 = 0; ks2 < 4; ks2++) {
                    int ks = ng * 4 + ks2;
                    int col = ks * 8 + tg;
                    unsigned a0 = *(const unsigned*)&sAb[ra0 + (col ^ swz)];
                    unsigned a1 = *(const unsigned*)&sAb[ra1 + (col ^ swz)];
                    unsigned a2 = *(const unsigned*)&sAb[ra0 + ((col + 4) ^ swz)];
                    unsigned a3 = *(const unsigned*)&sAb[ra1 + ((col + 4) ^ swz)];
                    int gk8 = (p * 8 + ks) * 8 + tg;
#pragma unroll
                    for (int g = 0; g < 3; g++) {
                        unsigned b0 = *(const unsigned*)&bw2[g * 4096 + (gk8 ^ swz)];
                        unsigned b1 = *(const unsigned*)&bw2[g * 4096 + ((gk8 + 4) ^ swz)];
                        mma16816(cB[g], a0, a1, a2, a3, b0, b1);
                    }
                }
            }
            __syncthreads();
            int m0r = mt * 16 + gID, nc = 2 * tg;
            if (ng == 1) {
#pragma unroll
                for (int g = 0; g < 3; g++) {
                    *(float2*)&sRed[m0r * 24 + g * 8 + nc]       = make_float2(cB[g][0], cB[g][1]);
                    *(float2*)&sRed[(m0r + 8) * 24 + g * 8 + nc] = make_float2(cB[g][2], cB[g][3]);
                }
            }
            __syncthreads();
            if (ng == 0) {
#pragma unroll
                for (int g = 0; g < 3; g++) {
                    float2 r0 = *(float2*)&sRed[m0r * 24 + g * 8 + nc];
                    float2 r1 = *(float2*)&sRed[(m0r + 8) * 24 + g * 8 + nc];
                    *(float2*)&sPre[3072 + m0r * 24 + g * 8 + nc]       = make_float2(cB[g][0] + r0.x, cB[g][1] + r0.y);
                    *(float2*)&sPre[3072 + (m0r + 8) * 24 + g * 8 + nc] = make_float2(cB[g][2] + r1.x, cB[g][3] + r1.y);
                }
            }
            __syncthreads();

            // ---- phase 3: L1 elementwise step t=i-2, publish h1, arrive bar1 ----
            int t = i - 2;
            float h1n[2];
#pragma unroll
            for (int d = 0; d < 2; d++) {
                int j = jj + d;
                float r = sigm(sPre[1536 + b * 24 + j]     + sBias[24 + j] +
                               sPre[3072 + b * 24 + j]     + sBias[48 + j]);
                float z = sigm(sPre[1536 + b * 24 + 8 + j] + sBias[32 + j] +
                               sPre[3072 + b * 24 + 8 + j] + sBias[56 + j]);
                float n = tanhf(sPre[1536 + b * 24 + 16 + j] + sBias[40 + j] +
                                r * (sPre[3072 + b * 24 + 16 + j] + sBias[64 + j]));
                h1n[d] = (1.0f - z) * n + z * sH1f[b * 8 + j];
            }
            sH1f[b * 8 + jj] = h1n[0]; sH1f[b * 8 + jj + 1] = h1n[1];
            g_h1[i & 1][b * 512 + ((j0 + jj) >> 1)] = __floats2half2_rn(h1n[0], h1n[1]);
            *(float2*)&out[((size_t)b * NT + t) * NH + j0 + jj] = make_float2(h1n[0], h1n[1]);
            if (hasFinal && t == NT - 1) {
                float* o2 = out + (size_t)NB * NT * NH;
                *(float2*)&o2[b * NH + j0 + jj] = make_float2(h1n[0], h1n[1]);
            }
            if (i <= NT) bar_arrive(&g_bar1);
            else __syncthreads();
        }

        if (i > NT) break;   // iter NT+1 runs phases 1-3 only

        // ---- phase 4: wait bar0, A1 GEMM: (Whh0|Wih1) @ h0^{i-1} ----
        if (i >= 1) bar_wait(&g_bar0, (unsigned)i * GCTA);
        {
            const uint4* A1 = (const uint4*)g_h0[(i + 1) & 1];  // (i-1)&1
            float cA[3][4] = {};
            issue_panel(A1, 0, 0);
            issue_panel(A1, 1, 1);
            for (int p = 0; p < 8; p++) {
                if (p < 7) cp_wait<1>(); else cp_wait<0>();
                __syncthreads();
                if (p + 2 < 8) issue_panel(A1, p + 2, (p + 2) % 3);
                const __half2* sAb = sA + (p % 3) * 4096;
                const int ra0 = (mt * 16 + gID) * 64, ra1 = ra0 + 512;
                const __half2* bw = &sW[ng * 12288 + gID * 512];
#pragma unroll
                for (int ks = 0; ks < 8; ks++) {
                    int col = ks * 8 + tg;
                    unsigned a0 = *(const unsigned*)&sAb[ra0 + (col ^ swz)];
                    unsigned a1 = *(const unsigned*)&sAb[ra1 + (col ^ swz)];
                    unsigned a2 = *(const unsigned*)&sAb[ra0 + ((col + 4) ^ swz)];
                    unsigned a3 = *(const unsigned*)&sAb[ra1 + ((col + 4) ^ swz)];
                    int gk8 = (p * 8 + ks) * 8 + tg;
#pragma unroll
                    for (int g = 0; g < 3; g++) {
                        unsigned b0 = *(const unsigned*)&bw[g * 4096 + (gk8 ^ swz)];
                        unsigned b1 = *(const unsigned*)&bw[g * 4096 + ((gk8 + 4) ^ swz)];
                        mma16816(cA[g], a0, a1, a2, a3, b0, b1);
                    }
                }
            }
            __syncthreads();
            int m0r = mt * 16 + gID, nc = 2 * tg;
            float* dst = (ng == 0) ? sPre : sPre + 1536;   // gh0 | gi1 (persists)
#pragma unroll
            for (int g = 0; g < 3; g++) {
                *(float2*)&dst[m0r * 24 + g * 8 + nc]       = make_float2(cA[g][0], cA[g][1]);
                *(float2*)&dst[(m0r + 8) * 24 + g * 8 + nc] = make_float2(cA[g][2], cA[g][3]);
            }
            __syncthreads();
        }

        // ---- phase 5: L0 elementwise step i, publish h0, arrive bar0 ----
        if (i < NT) {
            float gir[2] = {__low2float(pg0), __high2float(pg0)};
            float giz[2] = {__low2float(pg1), __high2float(pg1)};
            float gin[2] = {__low2float(pg2), __high2float(pg2)};
            float h0n[2];
#pragma unroll
            for (int d = 0; d < 2; d++) {
                int j = jj + d;
                float r = sigm(gir[d] + sPre[b * 24 + j]      + sBias[j]);
                float z = sigm(giz[d] + sPre[b * 24 + 8 + j]  + sBias[8 + j]);
                float n = tanhf(gin[d] + r * (sPre[b * 24 + 16 + j] + sBias[16 + j]));
                h0n[d] = (1.0f - z) * n + z * sH0f[b * 8 + j];
            }
            sH0f[b * 8 + jj] = h0n[0]; sH0f[b * 8 + jj + 1] = h0n[1];
            g_h0[i & 1][b * 512 + ((j0 + jj) >> 1)] = __floats2half2_rn(h0n[0], h0n[1]);
            bar_arrive(&g_bar0);
        }
    }
}

extern "C" void kernel_launch(void* const* d_in, const int* in_sizes, int n_in,
                              void* d_out, int out_size) {
    const float* x    = (const float*)d_in[0];
    const float* encH = (const float*)d_in[2];
    const float* Wih0 = (const float*)d_in[3];
    const float* Whh0 = (const float*)d_in[4];
    const float* bih0 = (const float*)d_in[5];
    const float* bhh0 = (const float*)d_in[6];
    const float* Wih1 = (const float*)d_in[7];
    const float* Whh1 = (const float*)d_in[8];
    const float* bih1 = (const float*)d_in[9];
    const float* bhh1 = (const float*)d_in[10];
    float* out = (float*)d_out;
    int hasFinal = (out_size >= NB * NT * NH + NB * NH) ? 1 : 0;

    cudaFuncSetAttribute(k_gru, cudaFuncAttributeMaxDynamicSharedMemorySize, SMEM_BYTES);

    k_cvt_x<<<16384, 256>>>((const float4*)x);
    k_cvt_w<<<1536, 256>>>((const float4*)Wih0);
    dim3 g1(48, 512);
    k_gi0<<<g1, 256>>>(bih0);
    k_gru<<<GCTA, 256, SMEM_BYTES>>>(out, Whh0, Wih1, Whh1,
                                     bhh0, bih1, bhh1, encH, hasFinal);
}